// round 10
// baseline (speedup 1.0000x reference)
#include <cuda_runtime.h>
#include <cuda_bf16.h>

// EdgeDecoder: per-edge bilinear scores over 5 relations + softmax-expected rating.
//   z_user  [100000, 64] f32
//   z_movie [ 50000, 64] f32
//   rel_emb [     5, 64] f32
//   edge_label_index [2, E] int (32 or 64 — detected at runtime)
//   out [E] f32
//
// R10 = R9 (best: 47.6us) + OCCUPANCY PUSH (profile: L1 64.7%, issue 55.6%,
// occ 52.2% -> latency-limited, regfile caps warps at 40 via regs=48):
//  - __launch_bounds__(256, 6): target 40 regs -> 6 CTAs/SM = 48 warps (+20%
//    resident warps and outstanding gathers).
//  - consecutive edge pairing (e, e+1): paired stores hit one 128B line; a
//    warp's idx loads span one contiguous 64B window.
//  - is64/is32 specialized loop copies under a grid-uniform branch.
// Retained: smem relD + softmax shift trick, 2-edge unroll, line-aligned
// lane mapping, value-splitting butterfly reduce (11 SHFL / 2 edges),
// shared softmax on lanes 0 & 4, ~1.5-wave grid.

constexpr int H = 64;

__device__ int   g_idx_is64;
__device__ float g_relD[4 * H];   // rel[r+1][h] - rel[0][h]

__global__ void prep_kernel(const float* __restrict__ rel_emb,
                            const void* __restrict__ edge_idx) {
    const int t = threadIdx.x;
    if (t < 4 * H) {
        const int r = t >> 6, h = t & 63;
        g_relD[t] = rel_emb[(r + 1) * H + h] - rel_emb[h];
    }
    if (t == 0) {
        // int64-vs-int32 index detection: true int64 indices are all in
        // [0, 50000). int32 data reinterpreted as int64 gives lo + hi*2^32
        // with hi ~ U[0,50000): passing all 8 checks is ~impossible.
        const long long* p = (const long long*)edge_idx;
        int is64 = 1;
        #pragma unroll
        for (int i = 0; i < 8; i++) {
            long long v = p[i];
            if (v < 0 || v >= 50000) is64 = 0;
        }
        g_idx_is64 = is64;
    }
}

__device__ __forceinline__ float softmax_expect4(float s0, float s1, float s2, float s3) {
    // score'[0] = 0, score'[r+1] = s_r
    float m = fmaxf(fmaxf(s0, s1), fmaxf(s2, s3));
    m = fmaxf(m, 0.f);
    const float e0 = __expf(s0 - m);
    const float e1 = __expf(s1 - m);
    const float e2 = __expf(s2 - m);
    const float e3 = __expf(s3 - m);
    const float den = __expf(-m) + e0 + e1 + e2 + e3;
    const float num = fmaf(e3, 4.f, fmaf(e2, 3.f, fmaf(e1, 2.f, e0)));
    return num / den;
}

template <bool IS64>
__device__ __forceinline__ void run_loop(
    const float* __restrict__ z_user,
    const float* __restrict__ z_movie,
    const void* __restrict__ edge_idx,
    float* __restrict__ out,
    int E, int g0, int ngroups, int sub, int gbase,
    const float* rel_lo, const float* rel_hi)
{
    const long long* p64 = (const long long*)edge_idx;
    const int*       p32 = (const int*)edge_idx;
    const int P = (E + 1) >> 1;   // number of edge pairs

    for (int gp = g0; gp < P; gp += ngroups) {
        const int  e    = 2 * gp;
        const int  e2   = e + 1;
        const bool has2 = (e2 < E);

        // ---- issue ALL loads up front: 2 index pairs, then 8 gather float4s
        int sA, dA, sB, dB;
        if (IS64) {
            sA = (int)__ldg(p64 + e);
            dA = (int)__ldg(p64 + (long long)E + e);
            sB = has2 ? (int)__ldg(p64 + e2) : 0;
            dB = has2 ? (int)__ldg(p64 + (long long)E + e2) : 0;
        } else {
            sA = __ldg(p32 + e);
            dA = __ldg(p32 + E + e);
            sB = has2 ? __ldg(p32 + e2) : 0;
            dB = has2 ? __ldg(p32 + E + e2) : 0;
        }

        const float* uA = z_user  + sA * H;
        const float* mA = z_movie + dA * H;
        const float* uB = z_user  + sB * H;
        const float* mB = z_movie + dB * H;

        const float4 zsA0 = *reinterpret_cast<const float4*>(uA + 4 * sub);
        const float4 zdA0 = *reinterpret_cast<const float4*>(mA + 4 * sub);
        const float4 zsA1 = *reinterpret_cast<const float4*>(uA + 32 + 4 * sub);
        const float4 zdA1 = *reinterpret_cast<const float4*>(mA + 32 + 4 * sub);
        const float4 zsB0 = *reinterpret_cast<const float4*>(uB + 4 * sub);
        const float4 zdB0 = *reinterpret_cast<const float4*>(mB + 4 * sub);
        const float4 zsB1 = *reinterpret_cast<const float4*>(uB + 32 + 4 * sub);
        const float4 zdB1 = *reinterpret_cast<const float4*>(mB + 32 + 4 * sub);

        // ---- elementwise products
        const float a0 = zsA0.x * zdA0.x, a1 = zsA0.y * zdA0.y,
                    a2 = zsA0.z * zdA0.z, a3 = zsA0.w * zdA0.w;
        const float a4 = zsA1.x * zdA1.x, a5 = zsA1.y * zdA1.y,
                    a6 = zsA1.z * zdA1.z, a7 = zsA1.w * zdA1.w;
        const float b0 = zsB0.x * zdB0.x, b1 = zsB0.y * zdB0.y,
                    b2 = zsB0.z * zdB0.z, b3 = zsB0.w * zdB0.w;
        const float b4 = zsB1.x * zdB1.x, b5 = zsB1.y * zdB1.y,
                    b6 = zsB1.z * zdB1.z, b7 = zsB1.w * zdB1.w;

        // ---- per-lane score partials (relD from smem, shared by A & B)
        float x[8];   // x[0..3]=scA_r, x[4..7]=scB_r
        #pragma unroll
        for (int r = 0; r < 4; r++) {
            const float4 r0 = *reinterpret_cast<const float4*>(rel_lo + r * H);
            const float4 r1 = *reinterpret_cast<const float4*>(rel_hi + r * H);
            x[r]     = fmaf(a0, r0.x, fmaf(a1, r0.y, fmaf(a2, r0.z, a3 * r0.w)))
                     + fmaf(a4, r1.x, fmaf(a5, r1.y, fmaf(a6, r1.z, a7 * r1.w)));
            x[4 + r] = fmaf(b0, r0.x, fmaf(b1, r0.y, fmaf(b2, r0.z, b3 * r0.w)))
                     + fmaf(b4, r1.x, fmaf(b5, r1.y, fmaf(b6, r1.z, b7 * r1.w)));
        }

        // ---- value-splitting butterfly reduce (8 values over 8 lanes)
        const bool hi4 = (sub & 4) != 0;
        float k4[4];
        #pragma unroll
        for (int i = 0; i < 4; i++) {
            const float keep = hi4 ? x[4 + i] : x[i];
            const float give = hi4 ? x[i]     : x[4 + i];
            k4[i] = keep + __shfl_xor_sync(0xffffffffu, give, 4);
        }
        const bool hi2 = (sub & 2) != 0;
        float k2[2];
        {
            const float kp0 = hi2 ? k4[2] : k4[0];
            const float gv0 = hi2 ? k4[0] : k4[2];
            const float kp1 = hi2 ? k4[3] : k4[1];
            const float gv1 = hi2 ? k4[1] : k4[3];
            k2[0] = kp0 + __shfl_xor_sync(0xffffffffu, gv0, 2);
            k2[1] = kp1 + __shfl_xor_sync(0xffffffffu, gv1, 2);
        }
        const bool hi1 = (sub & 1) != 0;
        const float kp = hi1 ? k2[1] : k2[0];
        const float gv = hi1 ? k2[0] : k2[1];
        const float tot = kp + __shfl_xor_sync(0xffffffffu, gv, 1);
        // lane gbase+r holds scA_r total; lane gbase+4+r holds scB_r total

        // ---- gather each half's 4 totals (lanes 0-3 get A, 4-7 get B)
        const int src = gbase + (sub & 4);
        const float v0 = __shfl_sync(0xffffffffu, tot, src + 0);
        const float v1 = __shfl_sync(0xffffffffu, tot, src + 1);
        const float v2 = __shfl_sync(0xffffffffu, tot, src + 2);
        const float v3 = __shfl_sync(0xffffffffu, tot, src + 3);

        // ---- one shared softmax execution covers both edges; paired stores
        // land in the same 128B line.
        if ((sub & 3) == 0) {
            const float r = softmax_expect4(v0, v1, v2, v3);
            if (sub == 0)  out[e]  = r;
            else if (has2) out[e2] = r;
        }
    }
}

__global__ __launch_bounds__(256, 6) void edge_decoder_kernel(
    const float* __restrict__ z_user,
    const float* __restrict__ z_movie,
    const void* __restrict__ edge_idx,
    float* __restrict__ out,
    int E)
{
    __shared__ float s_rel[4 * H];
    for (int t = threadIdx.x; t < 4 * H; t += 256)
        s_rel[t] = g_relD[t];
    __syncthreads();

    const int tid     = blockIdx.x * blockDim.x + threadIdx.x;
    const int sub     = threadIdx.x & 7;                 // lane within 8-lane group
    const int ngroups = (gridDim.x * blockDim.x) >> 3;   // total edge groups
    const int g0      = tid >> 3;
    const int gbase   = (threadIdx.x & 31) & ~7;         // group base lane in warp

    const float* rel_lo = s_rel + 4 * sub;        // floats [4sub..4sub+3]
    const float* rel_hi = s_rel + 32 + 4 * sub;   // floats [32+4sub..+3]

    if (g_idx_is64)
        run_loop<true >(z_user, z_movie, edge_idx, out, E, g0, ngroups, sub, gbase, rel_lo, rel_hi);
    else
        run_loop<false>(z_user, z_movie, edge_idx, out, E, g0, ngroups, sub, gbase, rel_lo, rel_hi);
}

extern "C" void kernel_launch(void* const* d_in, const int* in_sizes, int n_in,
                              void* d_out, int out_size) {
    const float* z_user  = (const float*)d_in[0];
    const float* z_movie = (const float*)d_in[1];
    const float* rel_emb = (const float*)d_in[2];
    const void*  eidx    = d_in[3];
    float* out = (float*)d_out;

    const int E = out_size;  // one rating per edge

    prep_kernel<<<1, 256>>>(rel_emb, eidx);

    // ~1.5 waves at 6 CTAs/SM (912 resident): backfill hides per-CTA spread.
    const int threads = 256;
    const int blocks  = 1368;
    edge_decoder_kernel<<<blocks, threads>>>(z_user, z_movie, eidx, out, E);
}

// round 11
// speedup vs baseline: 1.0672x; 1.0672x over previous
#include <cuda_runtime.h>
#include <cuda_bf16.h>

// EdgeDecoder: per-edge bilinear scores over 5 relations + softmax-expected rating.
//   z_user  [100000, 64] f32
//   z_movie [ 50000, 64] f32
//   rel_emb [     5, 64] f32
//   edge_label_index [2, E] int (32 or 64 — detected at runtime)
//   out [E] f32
//
// R11 = R9 (best: 47.6us; regs=48, strided pairing, 1216 blocks) + ONE change:
//   INDEX SOFTWARE PIPELINE inside the R9 for-loop body. Next iteration's 4
//   indices are prefetched (branchless, clamped) while the current gathers
//   are in flight -> per-iteration critical path drops from
//   idx_lat + gather_lat to gather_lat. Unlike R5's failed attempt, the loop
//   structure is unchanged and the body is lean (relD in smem, regs ~48).
// Also: branchless clamped B-index loads (has2 predication only on the final
// store) and is64/is32 template split (removes per-iteration predicate).
// NOT doing (R10 regressions): 40-reg cap, consecutive pairing.

constexpr int H = 64;

__device__ int   g_idx_is64;
__device__ float g_relD[4 * H];   // rel[r+1][h] - rel[0][h]

__global__ void prep_kernel(const float* __restrict__ rel_emb,
                            const void* __restrict__ edge_idx) {
    const int t = threadIdx.x;
    if (t < 4 * H) {
        const int r = t >> 6, h = t & 63;
        g_relD[t] = rel_emb[(r + 1) * H + h] - rel_emb[h];
    }
    if (t == 0) {
        // int64-vs-int32 index detection: true int64 indices are all in
        // [0, 50000). int32 data reinterpreted as int64 gives lo + hi*2^32
        // with hi ~ U[0,50000): passing all 8 checks is ~impossible.
        const long long* p = (const long long*)edge_idx;
        int is64 = 1;
        #pragma unroll
        for (int i = 0; i < 8; i++) {
            long long v = p[i];
            if (v < 0 || v >= 50000) is64 = 0;
        }
        g_idx_is64 = is64;
    }
}

__device__ __forceinline__ float softmax_expect4(float s0, float s1, float s2, float s3) {
    // score'[0] = 0, score'[r+1] = s_r
    float m = fmaxf(fmaxf(s0, s1), fmaxf(s2, s3));
    m = fmaxf(m, 0.f);
    const float e0 = __expf(s0 - m);
    const float e1 = __expf(s1 - m);
    const float e2 = __expf(s2 - m);
    const float e3 = __expf(s3 - m);
    const float den = __expf(-m) + e0 + e1 + e2 + e3;
    const float num = fmaf(e3, 4.f, fmaf(e2, 3.f, fmaf(e1, 2.f, e0)));
    return num / den;
}

template <bool IS64>
__device__ __forceinline__ void idx_load4(
    const void* __restrict__ edge_idx, int E,
    int eA, int eB, int& s1, int& d1, int& s2, int& d2)
{
    if (IS64) {
        const long long* p = (const long long*)edge_idx;
        s1 = (int)__ldg(p + eA);
        d1 = (int)__ldg(p + (long long)E + eA);
        s2 = (int)__ldg(p + eB);
        d2 = (int)__ldg(p + (long long)E + eB);
    } else {
        const int* p = (const int*)edge_idx;
        s1 = __ldg(p + eA);
        d1 = __ldg(p + E + eA);
        s2 = __ldg(p + eB);
        d2 = __ldg(p + E + eB);
    }
}

template <bool IS64>
__device__ __forceinline__ void run_loop(
    const float* __restrict__ z_user,
    const float* __restrict__ z_movie,
    const void* __restrict__ edge_idx,
    float* __restrict__ out,
    int E, int g0, int ngroups, int sub, int gbase,
    const float* rel_lo, const float* rel_hi)
{
    const int step = 2 * ngroups;

    // ---- prime the pipeline: indices for the first iteration (clamped B)
    int sA, dA, sB, dB;
    if (g0 < E) {
        const int e2c = (g0 + ngroups < E) ? (g0 + ngroups) : g0;
        idx_load4<IS64>(edge_idx, E, g0, e2c, sA, dA, sB, dB);
    } else {
        sA = dA = sB = dB = 0;
    }

    for (int e = g0; e < E; e += step) {
        const int  e2   = e + ngroups;
        const bool has2 = (e2 < E);

        // ---- issue the 8 gather float4s from the CURRENT (pre-loaded) idx
        const float* uA = z_user  + sA * H;
        const float* mA = z_movie + dA * H;
        const float* uB = z_user  + sB * H;
        const float* mB = z_movie + dB * H;

        const float4 zsA0 = *reinterpret_cast<const float4*>(uA + 4 * sub);
        const float4 zdA0 = *reinterpret_cast<const float4*>(mA + 4 * sub);
        const float4 zsA1 = *reinterpret_cast<const float4*>(uA + 32 + 4 * sub);
        const float4 zdA1 = *reinterpret_cast<const float4*>(mA + 32 + 4 * sub);
        const float4 zsB0 = *reinterpret_cast<const float4*>(uB + 4 * sub);
        const float4 zdB0 = *reinterpret_cast<const float4*>(mB + 4 * sub);
        const float4 zsB1 = *reinterpret_cast<const float4*>(uB + 32 + 4 * sub);
        const float4 zdB1 = *reinterpret_cast<const float4*>(mB + 32 + 4 * sub);

        // ---- prefetch NEXT iteration's indices while gathers are in flight
        // (branchless: clamped to safe addresses; values unused past the end)
        {
            const int en  = e + step;
            const int enc = (en < E) ? en : 0;
            const int en2 = en + ngroups;
            const int en2c = (en2 < E) ? en2 : 0;
            idx_load4<IS64>(edge_idx, E, enc, en2c, sA, dA, sB, dB);
        }

        // ---- elementwise products
        const float a0 = zsA0.x * zdA0.x, a1 = zsA0.y * zdA0.y,
                    a2 = zsA0.z * zdA0.z, a3 = zsA0.w * zdA0.w;
        const float a4 = zsA1.x * zdA1.x, a5 = zsA1.y * zdA1.y,
                    a6 = zsA1.z * zdA1.z, a7 = zsA1.w * zdA1.w;
        const float b0 = zsB0.x * zdB0.x, b1 = zsB0.y * zdB0.y,
                    b2 = zsB0.z * zdB0.z, b3 = zsB0.w * zdB0.w;
        const float b4 = zsB1.x * zdB1.x, b5 = zsB1.y * zdB1.y,
                    b6 = zsB1.z * zdB1.z, b7 = zsB1.w * zdB1.w;

        // ---- per-lane score partials (relD from smem, shared by A & B)
        float x[8];   // x[0..3]=scA_r, x[4..7]=scB_r
        #pragma unroll
        for (int r = 0; r < 4; r++) {
            const float4 r0 = *reinterpret_cast<const float4*>(rel_lo + r * H);
            const float4 r1 = *reinterpret_cast<const float4*>(rel_hi + r * H);
            x[r]     = fmaf(a0, r0.x, fmaf(a1, r0.y, fmaf(a2, r0.z, a3 * r0.w)))
                     + fmaf(a4, r1.x, fmaf(a5, r1.y, fmaf(a6, r1.z, a7 * r1.w)));
            x[4 + r] = fmaf(b0, r0.x, fmaf(b1, r0.y, fmaf(b2, r0.z, b3 * r0.w)))
                     + fmaf(b4, r1.x, fmaf(b5, r1.y, fmaf(b6, r1.z, b7 * r1.w)));
        }

        // ---- value-splitting butterfly reduce (8 values over 8 lanes)
        const bool hi4 = (sub & 4) != 0;
        float k4[4];
        #pragma unroll
        for (int i = 0; i < 4; i++) {
            const float keep = hi4 ? x[4 + i] : x[i];
            const float give = hi4 ? x[i]     : x[4 + i];
            k4[i] = keep + __shfl_xor_sync(0xffffffffu, give, 4);
        }
        const bool hi2 = (sub & 2) != 0;
        float k2[2];
        {
            const float kp0 = hi2 ? k4[2] : k4[0];
            const float gv0 = hi2 ? k4[0] : k4[2];
            const float kp1 = hi2 ? k4[3] : k4[1];
            const float gv1 = hi2 ? k4[1] : k4[3];
            k2[0] = kp0 + __shfl_xor_sync(0xffffffffu, gv0, 2);
            k2[1] = kp1 + __shfl_xor_sync(0xffffffffu, gv1, 2);
        }
        const bool hi1 = (sub & 1) != 0;
        const float kp = hi1 ? k2[1] : k2[0];
        const float gv = hi1 ? k2[0] : k2[1];
        const float tot = kp + __shfl_xor_sync(0xffffffffu, gv, 1);
        // lane gbase+r holds scA_r total; lane gbase+4+r holds scB_r total

        // ---- gather each half's 4 totals (lanes 0-3 get A, 4-7 get B)
        const int src = gbase + (sub & 4);
        const float v0 = __shfl_sync(0xffffffffu, tot, src + 0);
        const float v1 = __shfl_sync(0xffffffffu, tot, src + 1);
        const float v2 = __shfl_sync(0xffffffffu, tot, src + 2);
        const float v3 = __shfl_sync(0xffffffffu, tot, src + 3);

        // ---- one shared softmax execution covers both edges
        if ((sub & 3) == 0) {
            const float r = softmax_expect4(v0, v1, v2, v3);
            if (sub == 0)  out[e]  = r;
            else if (has2) out[e2] = r;
        }
    }
}

__global__ __launch_bounds__(256) void edge_decoder_kernel(
    const float* __restrict__ z_user,
    const float* __restrict__ z_movie,
    const void* __restrict__ edge_idx,
    float* __restrict__ out,
    int E)
{
    __shared__ float s_rel[4 * H];
    for (int t = threadIdx.x; t < 4 * H; t += 256)
        s_rel[t] = g_relD[t];
    __syncthreads();

    const int tid     = blockIdx.x * blockDim.x + threadIdx.x;
    const int sub     = threadIdx.x & 7;                 // lane within 8-lane group
    const int ngroups = (gridDim.x * blockDim.x) >> 3;   // total edge groups
    const int g0      = tid >> 3;
    const int gbase   = (threadIdx.x & 31) & ~7;         // group base lane in warp

    const float* rel_lo = s_rel + 4 * sub;        // floats [4sub..4sub+3]
    const float* rel_hi = s_rel + 32 + 4 * sub;   // floats [32+4sub..+3]

    if (g_idx_is64)
        run_loop<true >(z_user, z_movie, edge_idx, out, E, g0, ngroups, sub, gbase, rel_lo, rel_hi);
    else
        run_loop<false>(z_user, z_movie, edge_idx, out, E, g0, ngroups, sub, gbase, rel_lo, rel_hi);
}

extern "C" void kernel_launch(void* const* d_in, const int* in_sizes, int n_in,
                              void* d_out, int out_size) {
    const float* z_user  = (const float*)d_in[0];
    const float* z_movie = (const float*)d_in[1];
    const float* rel_emb = (const float*)d_in[2];
    const void*  eidx    = d_in[3];
    float* out = (float*)d_out;

    const int E = out_size;  // one rating per edge

    prep_kernel<<<1, 256>>>(rel_emb, eidx);

    // R9's best grid: 1216 CTAs (~1.6 waves at 5 CTAs/SM) — backfill beats
    // a single long wave.
    const int threads = 256;
    const int blocks  = 152 * 8;
    edge_decoder_kernel<<<blocks, threads>>>(z_user, z_movie, eidx, out, E);
}